// round 13
// baseline (speedup 1.0000x reference)
#include <cuda_runtime.h>
#include <cstdint>

// Warp processes 16 voxels per iteration (R9 structure, occ 8).
//   Load  : lane l -> voxel v = vbase + (l>>1), points 2*(l&1), 2*(l&1)+1 as ONE
//           256-bit ld.global.L2::evict_last.v4.b64 (32B aligned) -> read set
//           pinned in L2 across graph replays, half the LDG instruction count.
//   Scale : 1/max(cnt,1).
//   Remap : even lanes STS the 16 voxel sums; broadcast LDS per store round.
//   Store : 4 rounds of dense STG.128 (512B each) via __stcs (evict-first:
//           the 128MB write stream must not displace the pinned read set).
// Count dtype (int32 vs int64) probed in-kernel by warp 0 of each block;
// published as an index SHIFT (0 or 1) so the hot loop has no select.

__device__ __forceinline__ void ldg_el_32B(const float4* p, float4& a, float4& b) {
    unsigned long long r0, r1, r2, r3;
    asm volatile("ld.global.L2::evict_last.v4.b64 {%0,%1,%2,%3}, [%4];"
                 : "=l"(r0), "=l"(r1), "=l"(r2), "=l"(r3) : "l"(p));
    asm volatile("mov.b64 {%0,%1}, %2;" : "=f"(a.x), "=f"(a.y) : "l"(r0));
    asm volatile("mov.b64 {%0,%1}, %2;" : "=f"(a.z), "=f"(a.w) : "l"(r1));
    asm volatile("mov.b64 {%0,%1}, %2;" : "=f"(b.x), "=f"(b.y) : "l"(r2));
    asm volatile("mov.b64 {%0,%1}, %2;" : "=f"(b.z), "=f"(b.w) : "l"(r3));
}

__global__ __launch_bounds__(256, 8)
void radar_pointnet_kernel(const float4* __restrict__ vf,     // [V*4] float4
                           const float4* __restrict__ Wg,     // [32] float4 rows
                           const int*    __restrict__ counts_raw,
                           float4* __restrict__ out,          // [V*8] float4
                           int n_vox)
{
    __shared__ float4 sSum[8][2][16];   // [warp][parity][voxel-in-group]
    __shared__ int    sShift;

    // ---- In-block dtype probe (warp 0): int64 pairs must look like (0..4, 0).
    if (threadIdx.x < 32) {
        int i = threadIdx.x;
        int ok = 1;
        if (2 * i + 1 < n_vox) {        // safe under the int32 interpretation too
            int lo = counts_raw[2 * i];
            int hi = counts_raw[2 * i + 1];
            ok = (hi == 0) && (lo >= 0) && (lo <= 4);
        }
        unsigned all = __ballot_sync(0xFFFFFFFFu, ok);
        if (i == 0) sShift = (all == 0xFFFFFFFFu) ? 1 : 0;
    }
    __syncthreads();
    const int cshift = sShift;

    const int lane = threadIdx.x & 31;
    const int wrp  = threadIdx.x >> 5;
    const int col  = lane & 7;          // this lane's output float4 column
    const int vloc = lane >> 1;         // voxel-in-group this lane loads (0..15)
    const int vsel = lane >> 3;         // voxel-in-quad for store rounds (0..3)

    // W rows for channels [4*col, 4*col+4): registers, loaded once.
    const float4 w0 = Wg[col * 4 + 0];
    const float4 w1 = Wg[col * 4 + 1];
    const float4 w2 = Wg[col * 4 + 2];
    const float4 w3 = Wg[col * 4 + 3];

    const int groups  = (n_vox + 15) >> 4;
    const int warp_id = (blockIdx.x * blockDim.x + threadIdx.x) >> 5;
    const int nwarps  = (gridDim.x * blockDim.x) >> 5;

    int buf = 0;
    for (int g = warp_id; g < groups; g += nwarps, buf ^= 1) {
        const int vbase = g << 4;
        const int v     = vbase + vloc;
        const bool full = (vbase + 16 <= n_vox);

        float4 q0, q1;
        int cnt;
        if (full | (v < n_vox)) {
            // 32B-aligned: float4 index (v<<2) + 2*(lane&1) is even.
            ldg_el_32B(vf + (v << 2) + ((lane & 1) << 1), q0, q1);
            cnt = counts_raw[v << cshift];
        } else {
            q0 = q1 = make_float4(0.f, 0.f, 0.f, 0.f);
            cnt = 1;
        }

        // Pair-sum locally (FMA pipe), then one butterfly with the partner lane.
        float sx = q0.x + q1.x, sy = q0.y + q1.y;
        float sz = q0.z + q1.z, sw = q0.w + q1.w;
        sx += __shfl_xor_sync(0xFFFFFFFFu, sx, 1);
        sy += __shfl_xor_sync(0xFFFFFFFFu, sy, 1);
        sz += __shfl_xor_sync(0xFFFFFFFFu, sz, 1);
        sw += __shfl_xor_sync(0xFFFFFFFFu, sw, 1);

        const float inv = 1.0f / (float)(cnt > 1 ? cnt : 1);
        if ((lane & 1) == 0)
            sSum[wrp][buf][vloc] = make_float4(sx * inv, sy * inv, sz * inv, sw * inv);
        __syncwarp();

        if (full) {
            #pragma unroll
            for (int r = 0; r < 4; r++) {
                const float4 t = sSum[wrp][buf][r * 4 + vsel];   // broadcast LDS
                float4 o;
                o.x = t.x * w0.x + t.y * w0.y + t.z * w0.z + t.w * w0.w;
                o.y = t.x * w1.x + t.y * w1.y + t.z * w1.z + t.w * w1.w;
                o.z = t.x * w2.x + t.y * w2.y + t.z * w2.z + t.w * w2.w;
                o.w = t.x * w3.x + t.y * w3.y + t.z * w3.z + t.w * w3.w;
                __stcs(&out[(vbase << 3) + r * 32 + lane], o);   // dense 512B, evict-first
            }
        } else {
            #pragma unroll
            for (int r = 0; r < 4; r++) {
                if (vbase + r * 4 + vsel < n_vox) {
                    const float4 t = sSum[wrp][buf][r * 4 + vsel];
                    float4 o;
                    o.x = t.x * w0.x + t.y * w0.y + t.z * w0.z + t.w * w0.w;
                    o.y = t.x * w1.x + t.y * w1.y + t.z * w1.z + t.w * w1.w;
                    o.z = t.x * w2.x + t.y * w2.y + t.z * w2.z + t.w * w2.w;
                    o.w = t.x * w3.x + t.y * w3.y + t.z * w3.z + t.w * w3.w;
                    __stcs(&out[(vbase << 3) + r * 32 + lane], o);
                }
            }
        }
        // No trailing syncwarp: next iteration writes the other sSum buffer;
        // reuse two iterations out is ordered by the next mid-loop __syncwarp.
    }
}

extern "C" void kernel_launch(void* const* d_in, const int* in_sizes, int n_in,
                              void* d_out, int out_size)
{
    const float4* vf     = (const float4*)d_in[0];
    const float4* W      = (const float4*)d_in[1];
    const int*    counts = (const int*)d_in[2];
    float4*       out    = (float4*)d_out;
    int n_vox = in_sizes[2];
    if (n_vox <= 0) return;

    int block = 256;
    long long groups = ((long long)n_vox + 15) >> 4;
    long long max_blocks = (groups * 32 + block - 1) / block;  // at most 1 group/warp
    int grid = (int)((max_blocks < 1184) ? max_blocks : 1184); // 148 SMs x 8 blocks
    radar_pointnet_kernel<<<grid, block>>>(vf, W, counts, out, n_vox);
}

// round 14
// speedup vs baseline: 1.0156x; 1.0156x over previous
#include <cuda_runtime.h>
#include <cstdint>

// FINAL (R9 configuration — measured best at 39.5us kernel / 41.5us wall).
// Warp processes 16 voxels per iteration, occupancy 8 blocks/SM.
//   Load  : lane l -> voxel v = vbase + (l>>1), points 2*(l&1), 2*(l&1)+1
//           (two LDG.128, jointly dense 1024B/warp), local add, ONE xor-1
//           butterfly to complete the 4-point sum.
//   Scale : 1/max(cnt,1).
//   Remap : even lanes STS the 16 voxel sums; broadcast LDS per store round.
//   Store : 4 rounds of dense STG.128 (512B each) via __stcs (evict-first was
//           the best of {default, stcs, stwt, evict_last-loads} in A/B tests).
// Count dtype (int32 vs int64) probed in-kernel by warp 0 of each block;
// published as an index SHIFT (0 or 1) so the hot loop has no select.
// Perf model: 128MB mandatory writes at ~3.2TB/s write-drain + overlapped
// residual reads -> ~39.5us kernel; DRAM/L1/L2 all ~50-60%, confirmed
// invariant across five structural variants (write-stream roofline).
__global__ __launch_bounds__(256, 8)
void radar_pointnet_kernel(const float4* __restrict__ vf,     // [V*4] float4
                           const float4* __restrict__ Wg,     // [32] float4 rows
                           const int*    __restrict__ counts_raw,
                           float4* __restrict__ out,          // [V*8] float4
                           int n_vox)
{
    __shared__ float4 sSum[8][2][16];   // [warp][parity][voxel-in-group]
    __shared__ int    sShift;

    // ---- In-block dtype probe (warp 0): int64 pairs must look like (0..4, 0).
    if (threadIdx.x < 32) {
        int i = threadIdx.x;
        int ok = 1;
        if (2 * i + 1 < n_vox) {        // safe under the int32 interpretation too
            int lo = counts_raw[2 * i];
            int hi = counts_raw[2 * i + 1];
            ok = (hi == 0) && (lo >= 0) && (lo <= 4);
        }
        unsigned all = __ballot_sync(0xFFFFFFFFu, ok);
        if (i == 0) sShift = (all == 0xFFFFFFFFu) ? 1 : 0;
    }
    __syncthreads();
    const int cshift = sShift;

    const int lane = threadIdx.x & 31;
    const int wrp  = threadIdx.x >> 5;
    const int col  = lane & 7;          // this lane's output float4 column
    const int vloc = lane >> 1;         // voxel-in-group this lane loads (0..15)
    const int vsel = lane >> 3;         // voxel-in-quad for store rounds (0..3)

    // W rows for channels [4*col, 4*col+4): registers, loaded once.
    const float4 w0 = Wg[col * 4 + 0];
    const float4 w1 = Wg[col * 4 + 1];
    const float4 w2 = Wg[col * 4 + 2];
    const float4 w3 = Wg[col * 4 + 3];

    const int groups  = (n_vox + 15) >> 4;
    const int warp_id = (blockIdx.x * blockDim.x + threadIdx.x) >> 5;
    const int nwarps  = (gridDim.x * blockDim.x) >> 5;

    int buf = 0;
    for (int g = warp_id; g < groups; g += nwarps, buf ^= 1) {
        const int vbase = g << 4;
        const int v     = vbase + vloc;
        const bool full = (vbase + 16 <= n_vox);

        float4 q0, q1;
        int cnt;
        if (full | (v < n_vox)) {
            const float4* p = vf + (v << 2) + ((lane & 1) << 1);
            q0  = p[0];
            q1  = p[1];
            cnt = counts_raw[v << cshift];
        } else {
            q0 = q1 = make_float4(0.f, 0.f, 0.f, 0.f);
            cnt = 1;
        }

        // Pair-sum locally (FMA pipe), then one butterfly with the partner lane.
        float sx = q0.x + q1.x, sy = q0.y + q1.y;
        float sz = q0.z + q1.z, sw = q0.w + q1.w;
        sx += __shfl_xor_sync(0xFFFFFFFFu, sx, 1);
        sy += __shfl_xor_sync(0xFFFFFFFFu, sy, 1);
        sz += __shfl_xor_sync(0xFFFFFFFFu, sz, 1);
        sw += __shfl_xor_sync(0xFFFFFFFFu, sw, 1);

        const float inv = 1.0f / (float)(cnt > 1 ? cnt : 1);
        if ((lane & 1) == 0)
            sSum[wrp][buf][vloc] = make_float4(sx * inv, sy * inv, sz * inv, sw * inv);
        __syncwarp();

        if (full) {
            #pragma unroll
            for (int r = 0; r < 4; r++) {
                const float4 t = sSum[wrp][buf][r * 4 + vsel];   // broadcast LDS
                float4 o;
                o.x = t.x * w0.x + t.y * w0.y + t.z * w0.z + t.w * w0.w;
                o.y = t.x * w1.x + t.y * w1.y + t.z * w1.z + t.w * w1.w;
                o.z = t.x * w2.x + t.y * w2.y + t.z * w2.z + t.w * w2.w;
                o.w = t.x * w3.x + t.y * w3.y + t.z * w3.z + t.w * w3.w;
                __stcs(&out[(vbase << 3) + r * 32 + lane], o);   // dense 512B, evict-first
            }
        } else {
            #pragma unroll
            for (int r = 0; r < 4; r++) {
                if (vbase + r * 4 + vsel < n_vox) {
                    const float4 t = sSum[wrp][buf][r * 4 + vsel];
                    float4 o;
                    o.x = t.x * w0.x + t.y * w0.y + t.z * w0.z + t.w * w0.w;
                    o.y = t.x * w1.x + t.y * w1.y + t.z * w1.z + t.w * w1.w;
                    o.z = t.x * w2.x + t.y * w2.y + t.z * w2.z + t.w * w2.w;
                    o.w = t.x * w3.x + t.y * w3.y + t.z * w3.z + t.w * w3.w;
                    __stcs(&out[(vbase << 3) + r * 32 + lane], o);
                }
            }
        }
        // No trailing syncwarp: next iteration writes the other sSum buffer;
        // reuse two iterations out is ordered by the next mid-loop __syncwarp.
    }
}

extern "C" void kernel_launch(void* const* d_in, const int* in_sizes, int n_in,
                              void* d_out, int out_size)
{
    const float4* vf     = (const float4*)d_in[0];
    const float4* W      = (const float4*)d_in[1];
    const int*    counts = (const int*)d_in[2];
    float4*       out    = (float4*)d_out;
    int n_vox = in_sizes[2];
    if (n_vox <= 0) return;

    int block = 256;
    long long groups = ((long long)n_vox + 15) >> 4;
    long long max_blocks = (groups * 32 + block - 1) / block;  // at most 1 group/warp
    int grid = (int)((max_blocks < 1184) ? max_blocks : 1184); // 148 SMs x 8 blocks
    radar_pointnet_kernel<<<grid, block>>>(vf, W, counts, out, n_vox);
}